// round 15
// baseline (speedup 1.0000x reference)
#include <cuda_runtime.h>
#include <cuda_fp16.h>
#include <math.h>
#include <stdint.h>

#define Bdim 8
#define Tdim 1024
#define Fdim 256
#define Hdim 256
#define BT (Bdim*Tdim)          /* 8192 */
#define NBR 8
#define EPSV 1e-5f

// ---------------- scratch (static device globals; no allocations) -----------
__device__ __half g_real[(size_t)BT*Fdim];
__device__ __half g_imag[(size_t)BT*Fdim];
__device__ __half g_whq[(size_t)NBR*Fdim*Hdim];
__device__ __half g_whk[(size_t)NBR*Fdim*Hdim];
__device__ __half g_whv[(size_t)NBR*Fdim*Hdim];
__device__ __half g_q[(size_t)NBR*BT*Hdim];
__device__ __half g_k[(size_t)NBR*BT*Hdim];
__device__ __half g_v[(size_t)NBR*BT*Hdim];
__device__ __half g_oh[(size_t)NBR*BT*Hdim];   // normalized O, fp16, [bt][n][h]

// ---------------- helpers ----------------------------------------------------
__device__ __forceinline__ float ex2(float x) {
    float y;
    asm("ex2.approx.ftz.f32 %0, %1;" : "=f"(y) : "f"(x));
    return y;
}

__device__ __forceinline__ uint32_t smem_u32(const void* p) {
    uint32_t a;
    asm("{ .reg .u64 t; cvta.to.shared.u64 t, %1; cvt.u32.u64 %0, t; }"
        : "=r"(a) : "l"(p));
    return a;
}

__device__ __forceinline__ void mma_f16(float* d,
                                        uint32_t a0, uint32_t a1, uint32_t a2, uint32_t a3,
                                        uint32_t b0, uint32_t b1) {
    asm volatile(
        "mma.sync.aligned.m16n8k16.row.col.f32.f16.f16.f32 "
        "{%0,%1,%2,%3}, {%4,%5,%6,%7}, {%8,%9}, {%0,%1,%2,%3};"
        : "+f"(d[0]), "+f"(d[1]), "+f"(d[2]), "+f"(d[3])
        : "r"(a0), "r"(a1), "r"(a2), "r"(a3), "r"(b0), "r"(b1));
}

__device__ __forceinline__ void ldsm4(uint32_t& r0, uint32_t& r1, uint32_t& r2, uint32_t& r3,
                                      uint32_t a) {
    asm volatile("ldmatrix.sync.aligned.m8n8.x4.shared.b16 {%0,%1,%2,%3}, [%4];"
                 : "=r"(r0), "=r"(r1), "=r"(r2), "=r"(r3) : "r"(a));
}
__device__ __forceinline__ void ldsm4t(uint32_t& r0, uint32_t& r1, uint32_t& r2, uint32_t& r3,
                                       uint32_t a) {
    asm volatile("ldmatrix.sync.aligned.m8n8.x4.trans.shared.b16 {%0,%1,%2,%3}, [%4];"
                 : "=r"(r0), "=r"(r1), "=r"(r2), "=r"(r3) : "r"(a));
}

__device__ __forceinline__ void cp16(uint32_t dst, const void* src) {
    asm volatile("cp.async.cg.shared.global [%0], [%1], 16;" :: "r"(dst), "l"(src));
}
#define CP_COMMIT() asm volatile("cp.async.commit_group;" ::: "memory")
#define CP_WAIT(n)  asm volatile("cp.async.wait_group %0;" :: "n"(n) : "memory")

__device__ __forceinline__ uint32_t h2u(__half2 h) {
    return *reinterpret_cast<uint32_t*>(&h);
}

// ---------------- block reduction of 4 values (256 threads) -----------------
__device__ __forceinline__ void block_reduce_sum4(float v[4]) {
    __shared__ float buf[8][4];
    int lane = threadIdx.x & 31, wp = threadIdx.x >> 5;
#pragma unroll
    for (int k = 0; k < 4; k++) {
#pragma unroll
        for (int o = 16; o > 0; o >>= 1)
            v[k] += __shfl_xor_sync(0xffffffffu, v[k], o);
    }
    if (lane == 0) {
        buf[wp][0] = v[0]; buf[wp][1] = v[1]; buf[wp][2] = v[2]; buf[wp][3] = v[3];
    }
    __syncthreads();
#pragma unroll
    for (int k = 0; k < 4; k++) {
        float t = 0.f;
#pragma unroll
        for (int w = 0; w < 8; w++) t += buf[w][k];
        v[k] = t;
    }
}

// ---------------- fused: warp-per-row LN over F + W fp32->fp16 --------------
#define LN1_BLOCKS (BT / 8)   /* 1024: 8 rows per 256-thread block */
__global__ void ln1_wcvt_kernel(const float* __restrict__ x,
                                const float* __restrict__ w,
                                const float* __restrict__ b,
                                const float* __restrict__ Wq,
                                const float* __restrict__ Wk,
                                const float* __restrict__ Wv) {
    if (blockIdx.x >= LN1_BLOCKS) {
        int i = ((blockIdx.x - LN1_BLOCKS) * 256 + threadIdx.x) * 4;
        float4 a = *(const float4*)(Wq + i);
        float4 bb = *(const float4*)(Wk + i);
        float4 c = *(const float4*)(Wv + i);
        *(uint2*)(g_whq + i) = make_uint2(h2u(__floats2half2_rn(a.x, a.y)),
                                          h2u(__floats2half2_rn(a.z, a.w)));
        *(uint2*)(g_whk + i) = make_uint2(h2u(__floats2half2_rn(bb.x, bb.y)),
                                          h2u(__floats2half2_rn(bb.z, bb.w)));
        *(uint2*)(g_whv + i) = make_uint2(h2u(__floats2half2_rn(c.x, c.y)),
                                          h2u(__floats2half2_rn(c.z, c.w)));
        return;
    }
    int bt = blockIdx.x * 8 + (threadIdx.x >> 5);
    int lane = threadIdx.x & 31;
    const float2* xr = (const float2*)x + (size_t)bt * Fdim;

    float2 xv[8];
    float sr = 0.f, sr2 = 0.f, si = 0.f, si2 = 0.f;
#pragma unroll
    for (int k = 0; k < 8; k++) {
        xv[k] = xr[lane + 32 * k];
        sr += xv[k].x; sr2 += xv[k].x * xv[k].x;
        si += xv[k].y; si2 += xv[k].y * xv[k].y;
    }
#pragma unroll
    for (int o = 16; o > 0; o >>= 1) {
        sr  += __shfl_xor_sync(0xffffffffu, sr, o);
        sr2 += __shfl_xor_sync(0xffffffffu, sr2, o);
        si  += __shfl_xor_sync(0xffffffffu, si, o);
        si2 += __shfl_xor_sync(0xffffffffu, si2, o);
    }
    const float invF = 1.f / (float)Fdim;
    float mr = sr * invF, rr = rsqrtf(sr2 * invF - mr * mr + EPSV);
    float mi = si * invF, ri = rsqrtf(si2 * invF - mi * mi + EPSV);
#pragma unroll
    for (int k = 0; k < 8; k++) {
        int f = lane + 32 * k;
        float wf = w[f], bf = b[f];
        g_real[(size_t)bt * Fdim + f] = __float2half_rn((xv[k].x - mr) * rr * wf + bf);
        g_imag[(size_t)bt * Fdim + f] = __float2half_rn((xv[k].y - mi) * ri * wf + bf);
    }
}

// ---------------- batched QKV projection GEMM (double-buffered, safe) -------
#define AST 72
#define WST 136
#define ABUF (128*AST*2)     /* 18432 */
#define WBUF (64*WST*2)      /* 17408 */
#define GEMM2_SMEM (2*ABUF + 2*WBUF)   /* 71680 */
#define SC2 (0.0625f * 1.44269504f)

__global__ __launch_bounds__(256, 2) void qkv_gemm_kernel(
    const float* __restrict__ bq, const float* __restrict__ bk,
    const float* __restrict__ bv) {
    extern __shared__ char sgc[];
    uint32_t sb = smem_u32(sgc);

    int op = blockIdx.z;
    int n = op / 3, which = op - n * 3;
    int plane;
    const __half* Wh; const float* bias; __half* C;
    if (which == 0)      { plane = (n >> 1) & 1;  Wh = g_whq + (size_t)n * Fdim * Hdim; bias = bq + n * Hdim; C = g_q + (size_t)n * BT * Hdim; }
    else if (which == 1) { plane = n & 1;         Wh = g_whk + (size_t)n * Fdim * Hdim; bias = bk + n * Hdim; C = g_k + (size_t)n * BT * Hdim; }
    else                 { plane = __popc(n) & 1; Wh = g_whv + (size_t)n * Fdim * Hdim; bias = bv + n * Hdim; C = g_v + (size_t)n * BT * Hdim; }
    const __half* A = plane ? g_imag : g_real;
    const float oscale = (which == 0) ? SC2 : 1.0f;

    int row0 = blockIdx.x * 128, col0 = blockIdx.y * 128;
    int tid = threadIdx.x;
    int w = tid >> 5, lane = tid & 31;
    int r = lane >> 2, tg = lane & 3;
    int wr = w & 1, wc = w >> 1;
    int lrow = (lane & 7) + ((lane >> 3) & 1) * 8;
    int lcol = ((lane >> 4) & 1) * 8;

    float acc[4][4][4];
#pragma unroll
    for (int mt = 0; mt < 4; mt++)
#pragma unroll
        for (int nt = 0; nt < 4; nt++)
#pragma unroll
            for (int j = 0; j < 4; j++) acc[mt][nt][j] = 0.f;

    // prefetch chunk 0 into buffer 0
#pragma unroll
    for (int i = tid; i < 1024; i += 256) {
        int rr = i >> 3, seg = i & 7;
        cp16(sb + (rr * AST + seg * 8) * 2,
             A + (size_t)(row0 + rr) * Fdim + seg * 8);
    }
#pragma unroll
    for (int i = tid; i < 1024; i += 256) {
        int rr = i >> 4, seg = i & 15;
        cp16(sb + 2 * ABUF + (rr * WST + seg * 8) * 2,
             Wh + (size_t)rr * Hdim + col0 + seg * 8);
    }
    CP_COMMIT();

    for (int kc = 0; kc < 4; kc++) {
        CP_WAIT(0);
        __syncthreads();   // publish chunk kc; compute(kc-1) done (WAR-safe)
        if (kc < 3) {
            int nb = (kc + 1) & 1;
            int k0 = (kc + 1) * 64;
#pragma unroll
            for (int i = tid; i < 1024; i += 256) {
                int rr = i >> 3, seg = i & 7;
                cp16(sb + nb * ABUF + (rr * AST + seg * 8) * 2,
                     A + (size_t)(row0 + rr) * Fdim + k0 + seg * 8);
            }
#pragma unroll
            for (int i = tid; i < 1024; i += 256) {
                int rr = i >> 4, seg = i & 15;
                cp16(sb + 2 * ABUF + nb * WBUF + (rr * WST + seg * 8) * 2,
                     Wh + (size_t)(k0 + rr) * Hdim + col0 + seg * 8);
            }
            CP_COMMIT();
        }

        uint32_t sA = sb + (kc & 1) * ABUF;
        uint32_t sW = sb + 2 * ABUF + (kc & 1) * WBUF;
#pragma unroll
        for (int kt = 0; kt < 4; kt++) {
            uint32_t af[4][4];
#pragma unroll
            for (int mt = 0; mt < 4; mt++)
                ldsm4(af[mt][0], af[mt][1], af[mt][2], af[mt][3],
                      sA + ((64 * wr + 16 * mt + lrow) * AST + kt * 16 + lcol) * 2);
#pragma unroll
            for (int np = 0; np < 2; np++) {
                uint32_t b0, b1, b2, b3;
                ldsm4t(b0, b1, b2, b3,
                       sW + ((16 * kt + lrow) * WST + 32 * wc + np * 16 + lcol) * 2);
#pragma unroll
                for (int mt = 0; mt < 4; mt++) {
                    mma_f16(acc[mt][2 * np],     af[mt][0], af[mt][1], af[mt][2], af[mt][3], b0, b1);
                    mma_f16(acc[mt][2 * np + 1], af[mt][0], af[mt][1], af[mt][2], af[mt][3], b2, b3);
                }
            }
        }
    }

#pragma unroll
    for (int mt = 0; mt < 4; mt++) {
        int row = row0 + 64 * wr + 16 * mt + r;
#pragma unroll
        for (int nt = 0; nt < 4; nt++) {
            int col = col0 + 32 * wc + 8 * nt + 2 * tg;
            float b0 = bias[col], b1 = bias[col + 1];
            __half2 h0 = __floats2half2_rn((acc[mt][nt][0] + b0) * oscale,
                                           (acc[mt][nt][1] + b1) * oscale);
            __half2 h1 = __floats2half2_rn((acc[mt][nt][2] + b0) * oscale,
                                           (acc[mt][nt][3] + b1) * oscale);
            *(__half2*)(C + (size_t)row * Hdim + col) = h0;
            *(__half2*)(C + (size_t)(row + 8) * Hdim + col) = h1;
        }
    }
}

// ---------------- flash attention (64q CTA, occupancy 2) --------------------
// CTA: 64 queries, 256 threads / 8 warps, 32-key tiles double-buffered.
//  S phase:  warp = 16 rows x 16 keys. sr = 16*(w&3), key half skh = w>>2.
//  P 64x32 fp16 via smem (stride 40 halves, conflict-free).
//  PV phase: warp = 32 rows x 64 H. rb2 = (w&3)>>1, hq = 2*(w&1) | skh.
//  P handoff: producers == consumers == {w : (w&3)>>1 == rb2}, named 128-bar.
// Pipeline per tile: CP_WAIT(0) -> sync -> prefetch(j+1) -> compute(j) (WAR-safe).
// No-max softmax; O normalized by fp32 row sums, written fp16 [bt][n][h].
// smem ~104.5 KB -> 2 CTAs/SM; regs ~115 (oacc 64 + sacc 8) -> no spill.
#define QST4 264
#define QBYTES (64*QST4*2)              /* 33792 */
#define KVB (32*QST4*2)                 /* 16896 */
#define SM4_Q 0
#define SM4_K QBYTES                    /* 33792 */
#define SM4_V (SM4_K + 2*KVB)           /* 67584 */
#define SM4_P (SM4_V + 2*KVB)           /* 101376 */
#define PST4 40
#define SM4_R (SM4_P + 64*PST4*2)       /* 106496 */
#define ATT4_SMEM (SM4_R + 512)         /* 107008 */

__global__ __launch_bounds__(256, 2) void attn_kernel() {
    extern __shared__ char smc[];
    uint32_t sb = smem_u32(smc);
    int tid = threadIdx.x;
    int w = tid >> 5, lane = tid & 31;
    int r = lane >> 2, tg = lane & 3;
    int lrow = (lane & 7) + ((lane >> 3) & 1) * 8;
    int lcol = ((lane >> 4) & 1) * 8;
    int wr4 = w & 3;                 // S 16-row block
    int skh = w >> 2;                // S key half (0/1)
    int sr  = 16 * wr4;
    int rb2 = wr4 >> 1;              // PV 32-row block
    int hq  = ((w & 1) << 1) | skh;  // PV H quarter (0..3)

    int qt = blockIdx.x, b = blockIdx.y, n = blockIdx.z;
    size_t rowbase = ((size_t)n * Bdim + b) * Tdim;
    const __half* Qg = g_q + (rowbase + (size_t)qt * 64) * Hdim;
    const __half* Kg0 = g_k + rowbase * Hdim;
    const __half* Vg0 = g_v + rowbase * Hdim;

    // ---- Q (64 rows) + K/V tile 0 (32 rows each) ----
#pragma unroll
    for (int i = tid; i < 2048; i += 256) {
        int rr = i >> 5, seg = i & 31;
        cp16(sb + SM4_Q + (rr * QST4 + seg * 8) * 2, Qg + rr * 256 + seg * 8);
    }
#pragma unroll
    for (int i = tid; i < 1024; i += 256) {
        int rr = i >> 5, seg = i & 31;
        cp16(sb + SM4_K + (rr * QST4 + seg * 8) * 2, Kg0 + rr * 256 + seg * 8);
        cp16(sb + SM4_V + (rr * QST4 + seg * 8) * 2, Vg0 + rr * 256 + seg * 8);
    }
    CP_COMMIT();

    float oacc[2][8][4];
#pragma unroll
    for (int g = 0; g < 2; g++)
#pragma unroll
        for (int i = 0; i < 8; i++)
#pragma unroll
            for (int j = 0; j < 4; j++) oacc[g][i][j] = 0.f;
    float lac0 = 0.f, lac1 = 0.f;

    for (int j = 0; j < 32; j++) {
        CP_WAIT(0);
        __syncthreads();   // publish tile j; compute(j-1) done (WAR-safe)
        if (j + 1 < 32) {
            int nb = (j + 1) & 1;
            const __half* Kg = Kg0 + (size_t)(j + 1) * 32 * 256;
            const __half* Vg = Vg0 + (size_t)(j + 1) * 32 * 256;
#pragma unroll
            for (int i = tid; i < 1024; i += 256) {
                int rr = i >> 5, seg = i & 31;
                cp16(sb + SM4_K + nb * KVB + (rr * QST4 + seg * 8) * 2,
                     Kg + rr * 256 + seg * 8);
                cp16(sb + SM4_V + nb * KVB + (rr * QST4 + seg * 8) * 2,
                     Vg + rr * 256 + seg * 8);
            }
            CP_COMMIT();
        }

        uint32_t kbuf = sb + SM4_K + (j & 1) * KVB;
        uint32_t vbuf = sb + SM4_V + (j & 1) * KVB;

        // ---- S = Q K^T : warp 16 rows x 16 keys, K=256 ----
        float sacc[2][4];
#pragma unroll
        for (int i = 0; i < 2; i++)
#pragma unroll
            for (int jj = 0; jj < 4; jj++) sacc[i][jj] = 0.f;

#pragma unroll
        for (int c = 0; c < 16; c++) {
            int k0 = c * 16;
            uint32_t a0, a1, a2, a3;
            ldsm4(a0, a1, a2, a3,
                  sb + SM4_Q + ((sr + lrow) * QST4 + k0 + lcol) * 2);
            uint32_t b0, b1, b2, b3;
            ldsm4(b0, b1, b2, b3,
                  kbuf + ((16 * skh + lrow) * QST4 + k0 + lcol) * 2);
            mma_f16(sacc[0], a0, a1, a2, a3, b0, b2);
            mma_f16(sacc[1], a0, a1, a2, a3, b1, b3);
        }

        // ---- softmax: P = 2^S -> smem; row sums (this warp's 16 keys) ----
        {
            float l0 = 0.f, l1 = 0.f;
#pragma unroll
            for (int nt = 0; nt < 2; nt++) {
                float e0 = ex2(sacc[nt][0]);
                float e1 = ex2(sacc[nt][1]);
                float e2 = ex2(sacc[nt][2]);
                float e3 = ex2(sacc[nt][3]);
                __half2 h01 = __floats2half2_rn(e0, e1);
                __half2 h23 = __floats2half2_rn(e2, e3);
                int col = 16 * skh + 8 * nt + 2 * tg;
                *(__half2*)(smc + SM4_P + ((sr + r) * PST4 + col) * 2) = h01;
                *(__half2*)(smc + SM4_P + ((sr + 8 + r) * PST4 + col) * 2) = h23;
                float2 f01 = __half22float2(h01);
                float2 f23 = __half22float2(h23);
                l0 += f01.x + f01.y;
                l1 += f23.x + f23.y;
            }
            l0 += __shfl_xor_sync(0xffffffffu, l0, 1);
            l0 += __shfl_xor_sync(0xffffffffu, l0, 2);
            l1 += __shfl_xor_sync(0xffffffffu, l1, 1);
            l1 += __shfl_xor_sync(0xffffffffu, l1, 2);
            lac0 += l0;
            lac1 += l1;
        }
        // P handoff: named 128-thread barrier over {w : (w&3)>>1 == rb2}
        asm volatile("bar.sync %0, 128;" :: "r"(rb2 + 1) : "memory");

        // ---- O += P V : warp 32 rows x 64 H, K = 32 keys ----
#pragma unroll
        for (int pk = 0; pk < 2; pk++) {
            uint32_t pf0[4], pf1[4];
            ldsm4(pf0[0], pf0[1], pf0[2], pf0[3],
                  sb + SM4_P + ((32 * rb2 + lrow) * PST4 + 16 * pk + lcol) * 2);
            ldsm4(pf1[0], pf1[1], pf1[2], pf1[3],
                  sb + SM4_P + ((32 * rb2 + 16 + lrow) * PST4 + 16 * pk + lcol) * 2);
#pragma unroll
            for (int vg = 0; vg < 4; vg++) {
                uint32_t v0, v1, v2, v3;
                ldsm4t(v0, v1, v2, v3,
                       vbuf + ((16 * pk + lrow) * QST4 + 64 * hq + 16 * vg + lcol) * 2);
                mma_f16(oacc[0][2 * vg],     pf0[0], pf0[1], pf0[2], pf0[3], v0, v1);
                mma_f16(oacc[0][2 * vg + 1], pf0[0], pf0[1], pf0[2], pf0[3], v2, v3);
                mma_f16(oacc[1][2 * vg],     pf1[0], pf1[1], pf1[2], pf1[3], v0, v1);
                mma_f16(oacc[1][2 * vg + 1], pf1[0], pf1[1], pf1[2], pf1[3], v2, v3);
            }
        }
    }

    // ---- merge row sums across key halves, normalize, write fp16 -----------
    float* red = (float*)(smc + SM4_R);
    if (tg == 0) {
        red[skh * 64 + sr + r]     = lac0;
        red[skh * 64 + sr + 8 + r] = lac1;
    }
    __syncthreads();
    size_t btbase = (size_t)b * Tdim + (size_t)qt * 64;
#pragma unroll
    for (int g = 0; g < 2; g++) {
        int row0 = 32 * rb2 + 16 * g + r;
        float inv0 = 1.f / (red[row0] + red[64 + row0]);
        float inv1 = 1.f / (red[row0 + 8] + red[64 + row0 + 8]);
        __half* Og  = g_oh + ((btbase + row0) * NBR + n) * Hdim;
        __half* Og8 = g_oh + ((btbase + row0 + 8) * NBR + n) * Hdim;
#pragma unroll
        for (int nt = 0; nt < 8; nt++) {
            int col = 64 * hq + 8 * nt + 2 * tg;
            *(__half2*)(Og + col)  = __floats2half2_rn(oacc[g][nt][0] * inv0,
                                                       oacc[g][nt][1] * inv0);
            *(__half2*)(Og8 + col) = __floats2half2_rn(oacc[g][nt][2] * inv1,
                                                       oacc[g][nt][3] * inv1);
        }
    }
}

// ---------------- combine branches + LN over H, write output ----------------
__global__ void ln2_kernel(const float* __restrict__ w2,
                           const float* __restrict__ b2,
                           float* __restrict__ out) {
    int bt = blockIdx.x, h = threadIdx.x;
    const __half* ob = g_oh + (size_t)bt * NBR * Hdim;
    float o0 = __half2float(ob[h]);
    float o1 = __half2float(ob[Hdim + h]);
    float o2 = __half2float(ob[2 * Hdim + h]);
    float o3 = __half2float(ob[3 * Hdim + h]);
    float o4 = __half2float(ob[4 * Hdim + h]);
    float o5 = __half2float(ob[5 * Hdim + h]);
    float o6 = __half2float(ob[6 * Hdim + h]);
    float o7 = __half2float(ob[7 * Hdim + h]);
    float rc = o0 - o1 - o2 - o3;
    float ic = o4 + o5 + o6 - o7;
    float v[4] = {rc, rc * rc, ic, ic * ic};
    block_reduce_sum4(v);
    const float invH = 1.f / (float)Hdim;
    float mr = v[0] * invH, vr = v[1] * invH - mr * mr;
    float mi = v[2] * invH, vi = v[3] * invH - mi * mi;
    float wr = w2[h], br = b2[h];
    float2 ov;
    ov.x = (rc - mr) * rsqrtf(vr + EPSV) * wr + br;
    ov.y = (ic - mi) * rsqrtf(vi + EPSV) * wr + br;
    ((float2*)out)[(size_t)bt * Hdim + h] = ov;
}

// ---------------- launch ----------------------------------------------------
extern "C" void kernel_launch(void* const* d_in, const int* in_sizes, int n_in,
                              void* d_out, int out_size) {
    const float* x    = (const float*)d_in[0];
    const float* Wq   = (const float*)d_in[1];
    const float* bq   = (const float*)d_in[2];
    const float* Wk   = (const float*)d_in[3];
    const float* bk   = (const float*)d_in[4];
    const float* Wv   = (const float*)d_in[5];
    const float* bv   = (const float*)d_in[6];
    const float* ln1w = (const float*)d_in[7];
    const float* ln1b = (const float*)d_in[8];
    const float* ln2w = (const float*)d_in[9];
    const float* ln2b = (const float*)d_in[10];
    float* out = (float*)d_out;

    ln1_wcvt_kernel<<<LN1_BLOCKS + 512, 256>>>(x, ln1w, ln1b, Wq, Wk, Wv);

    cudaFuncSetAttribute(qkv_gemm_kernel, cudaFuncAttributeMaxDynamicSharedMemorySize,
                         GEMM2_SMEM);
    qkv_gemm_kernel<<<dim3(BT / 128, Hdim / 128, 24), 256, GEMM2_SMEM>>>(bq, bk, bv);

    cudaFuncSetAttribute(attn_kernel, cudaFuncAttributeMaxDynamicSharedMemorySize,
                         ATT4_SMEM);
    attn_kernel<<<dim3(Tdim / 64, Bdim, NBR), 256, ATT4_SMEM>>>();

    ln2_kernel<<<BT, Hdim>>>(ln2w, ln2b, out);
}

// round 16
// speedup vs baseline: 1.0603x; 1.0603x over previous
#include <cuda_runtime.h>
#include <cuda_fp16.h>
#include <math.h>
#include <stdint.h>

#define Bdim 8
#define Tdim 1024
#define Fdim 256
#define Hdim 256
#define BT (Bdim*Tdim)          /* 8192 */
#define NBR 8
#define EPSV 1e-5f

// ---------------- scratch (static device globals; no allocations) -----------
__device__ __half g_real[(size_t)BT*Fdim];
__device__ __half g_imag[(size_t)BT*Fdim];
__device__ __half g_whq[(size_t)NBR*Fdim*Hdim];
__device__ __half g_whk[(size_t)NBR*Fdim*Hdim];
__device__ __half g_whv[(size_t)NBR*Fdim*Hdim];
__device__ __half g_q[(size_t)NBR*BT*Hdim];
__device__ __half g_k[(size_t)NBR*BT*Hdim];
__device__ __half g_v[(size_t)NBR*BT*Hdim];
__device__ __half g_oh[(size_t)NBR*BT*Hdim];   // normalized O, fp16, [bt][n][h]

// ---------------- helpers ----------------------------------------------------
__device__ __forceinline__ float ex2(float x) {
    float y;
    asm("ex2.approx.ftz.f32 %0, %1;" : "=f"(y) : "f"(x));
    return y;
}

__device__ __forceinline__ uint32_t smem_u32(const void* p) {
    uint32_t a;
    asm("{ .reg .u64 t; cvta.to.shared.u64 t, %1; cvt.u32.u64 %0, t; }"
        : "=r"(a) : "l"(p));
    return a;
}

__device__ __forceinline__ void mma_f16(float* d,
                                        uint32_t a0, uint32_t a1, uint32_t a2, uint32_t a3,
                                        uint32_t b0, uint32_t b1) {
    asm volatile(
        "mma.sync.aligned.m16n8k16.row.col.f32.f16.f16.f32 "
        "{%0,%1,%2,%3}, {%4,%5,%6,%7}, {%8,%9}, {%0,%1,%2,%3};"
        : "+f"(d[0]), "+f"(d[1]), "+f"(d[2]), "+f"(d[3])
        : "r"(a0), "r"(a1), "r"(a2), "r"(a3), "r"(b0), "r"(b1));
}

__device__ __forceinline__ void ldsm4(uint32_t& r0, uint32_t& r1, uint32_t& r2, uint32_t& r3,
                                      uint32_t a) {
    asm volatile("ldmatrix.sync.aligned.m8n8.x4.shared.b16 {%0,%1,%2,%3}, [%4];"
                 : "=r"(r0), "=r"(r1), "=r"(r2), "=r"(r3) : "r"(a));
}
__device__ __forceinline__ void ldsm4t(uint32_t& r0, uint32_t& r1, uint32_t& r2, uint32_t& r3,
                                       uint32_t a) {
    asm volatile("ldmatrix.sync.aligned.m8n8.x4.trans.shared.b16 {%0,%1,%2,%3}, [%4];"
                 : "=r"(r0), "=r"(r1), "=r"(r2), "=r"(r3) : "r"(a));
}

__device__ __forceinline__ void cp16(uint32_t dst, const void* src) {
    asm volatile("cp.async.cg.shared.global [%0], [%1], 16;" :: "r"(dst), "l"(src));
}
#define CP_COMMIT() asm volatile("cp.async.commit_group;" ::: "memory")
#define CP_WAIT(n)  asm volatile("cp.async.wait_group %0;" :: "n"(n) : "memory")

__device__ __forceinline__ uint32_t h2u(__half2 h) {
    return *reinterpret_cast<uint32_t*>(&h);
}

// ---------------- block reduction of 4 values (256 threads) -----------------
__device__ __forceinline__ void block_reduce_sum4(float v[4]) {
    __shared__ float buf[8][4];
    int lane = threadIdx.x & 31, wp = threadIdx.x >> 5;
#pragma unroll
    for (int k = 0; k < 4; k++) {
#pragma unroll
        for (int o = 16; o > 0; o >>= 1)
            v[k] += __shfl_xor_sync(0xffffffffu, v[k], o);
    }
    if (lane == 0) {
        buf[wp][0] = v[0]; buf[wp][1] = v[1]; buf[wp][2] = v[2]; buf[wp][3] = v[3];
    }
    __syncthreads();
#pragma unroll
    for (int k = 0; k < 4; k++) {
        float t = 0.f;
#pragma unroll
        for (int w = 0; w < 8; w++) t += buf[w][k];
        v[k] = t;
    }
}

// ---------------- fused: warp-per-row LN over F + W fp32->fp16 --------------
#define LN1_BLOCKS (BT / 8)   /* 1024: 8 rows per 256-thread block */
__global__ void ln1_wcvt_kernel(const float* __restrict__ x,
                                const float* __restrict__ w,
                                const float* __restrict__ b,
                                const float* __restrict__ Wq,
                                const float* __restrict__ Wk,
                                const float* __restrict__ Wv) {
    if (blockIdx.x >= LN1_BLOCKS) {
        int i = ((blockIdx.x - LN1_BLOCKS) * 256 + threadIdx.x) * 4;
        float4 a = *(const float4*)(Wq + i);
        float4 bb = *(const float4*)(Wk + i);
        float4 c = *(const float4*)(Wv + i);
        *(uint2*)(g_whq + i) = make_uint2(h2u(__floats2half2_rn(a.x, a.y)),
                                          h2u(__floats2half2_rn(a.z, a.w)));
        *(uint2*)(g_whk + i) = make_uint2(h2u(__floats2half2_rn(bb.x, bb.y)),
                                          h2u(__floats2half2_rn(bb.z, bb.w)));
        *(uint2*)(g_whv + i) = make_uint2(h2u(__floats2half2_rn(c.x, c.y)),
                                          h2u(__floats2half2_rn(c.z, c.w)));
        return;
    }
    int bt = blockIdx.x * 8 + (threadIdx.x >> 5);
    int lane = threadIdx.x & 31;
    const float2* xr = (const float2*)x + (size_t)bt * Fdim;

    float2 xv[8];
    float sr = 0.f, sr2 = 0.f, si = 0.f, si2 = 0.f;
#pragma unroll
    for (int k = 0; k < 8; k++) {
        xv[k] = xr[lane + 32 * k];
        sr += xv[k].x; sr2 += xv[k].x * xv[k].x;
        si += xv[k].y; si2 += xv[k].y * xv[k].y;
    }
#pragma unroll
    for (int o = 16; o > 0; o >>= 1) {
        sr  += __shfl_xor_sync(0xffffffffu, sr, o);
        sr2 += __shfl_xor_sync(0xffffffffu, sr2, o);
        si  += __shfl_xor_sync(0xffffffffu, si, o);
        si2 += __shfl_xor_sync(0xffffffffu, si2, o);
    }
    const float invF = 1.f / (float)Fdim;
    float mr = sr * invF, rr = rsqrtf(sr2 * invF - mr * mr + EPSV);
    float mi = si * invF, ri = rsqrtf(si2 * invF - mi * mi + EPSV);
#pragma unroll
    for (int k = 0; k < 8; k++) {
        int f = lane + 32 * k;
        float wf = w[f], bf = b[f];
        g_real[(size_t)bt * Fdim + f] = __float2half_rn((xv[k].x - mr) * rr * wf + bf);
        g_imag[(size_t)bt * Fdim + f] = __float2half_rn((xv[k].y - mi) * ri * wf + bf);
    }
}

// ---------------- batched QKV projection GEMM (double-buffered, safe) -------
#define AST 72
#define WST 136
#define ABUF (128*AST*2)     /* 18432 */
#define WBUF (64*WST*2)      /* 17408 */
#define GEMM2_SMEM (2*ABUF + 2*WBUF)   /* 71680 */
#define SC2 (0.0625f * 1.44269504f)

__global__ __launch_bounds__(256, 2) void qkv_gemm_kernel(
    const float* __restrict__ bq, const float* __restrict__ bk,
    const float* __restrict__ bv) {
    extern __shared__ char sgc[];
    uint32_t sb = smem_u32(sgc);

    int op = blockIdx.z;
    int n = op / 3, which = op - n * 3;
    int plane;
    const __half* Wh; const float* bias; __half* C;
    if (which == 0)      { plane = (n >> 1) & 1;  Wh = g_whq + (size_t)n * Fdim * Hdim; bias = bq + n * Hdim; C = g_q + (size_t)n * BT * Hdim; }
    else if (which == 1) { plane = n & 1;         Wh = g_whk + (size_t)n * Fdim * Hdim; bias = bk + n * Hdim; C = g_k + (size_t)n * BT * Hdim; }
    else                 { plane = __popc(n) & 1; Wh = g_whv + (size_t)n * Fdim * Hdim; bias = bv + n * Hdim; C = g_v + (size_t)n * BT * Hdim; }
    const __half* A = plane ? g_imag : g_real;
    const float oscale = (which == 0) ? SC2 : 1.0f;

    int row0 = blockIdx.x * 128, col0 = blockIdx.y * 128;
    int tid = threadIdx.x;
    int w = tid >> 5, lane = tid & 31;
    int r = lane >> 2, tg = lane & 3;
    int wr = w & 1, wc = w >> 1;
    int lrow = (lane & 7) + ((lane >> 3) & 1) * 8;
    int lcol = ((lane >> 4) & 1) * 8;

    float acc[4][4][4];
#pragma unroll
    for (int mt = 0; mt < 4; mt++)
#pragma unroll
        for (int nt = 0; nt < 4; nt++)
#pragma unroll
            for (int j = 0; j < 4; j++) acc[mt][nt][j] = 0.f;

    // prefetch chunk 0 into buffer 0
#pragma unroll
    for (int i = tid; i < 1024; i += 256) {
        int rr = i >> 3, seg = i & 7;
        cp16(sb + (rr * AST + seg * 8) * 2,
             A + (size_t)(row0 + rr) * Fdim + seg * 8);
    }
#pragma unroll
    for (int i = tid; i < 1024; i += 256) {
        int rr = i >> 4, seg = i & 15;
        cp16(sb + 2 * ABUF + (rr * WST + seg * 8) * 2,
             Wh + (size_t)rr * Hdim + col0 + seg * 8);
    }
    CP_COMMIT();

    for (int kc = 0; kc < 4; kc++) {
        CP_WAIT(0);
        __syncthreads();   // publish chunk kc; compute(kc-1) done (WAR-safe)
        if (kc < 3) {
            int nb = (kc + 1) & 1;
            int k0 = (kc + 1) * 64;
#pragma unroll
            for (int i = tid; i < 1024; i += 256) {
                int rr = i >> 3, seg = i & 7;
                cp16(sb + nb * ABUF + (rr * AST + seg * 8) * 2,
                     A + (size_t)(row0 + rr) * Fdim + k0 + seg * 8);
            }
#pragma unroll
            for (int i = tid; i < 1024; i += 256) {
                int rr = i >> 4, seg = i & 15;
                cp16(sb + 2 * ABUF + nb * WBUF + (rr * WST + seg * 8) * 2,
                     Wh + (size_t)(k0 + rr) * Hdim + col0 + seg * 8);
            }
            CP_COMMIT();
        }

        uint32_t sA = sb + (kc & 1) * ABUF;
        uint32_t sW = sb + 2 * ABUF + (kc & 1) * WBUF;
#pragma unroll
        for (int kt = 0; kt < 4; kt++) {
            uint32_t af[4][4];
#pragma unroll
            for (int mt = 0; mt < 4; mt++)
                ldsm4(af[mt][0], af[mt][1], af[mt][2], af[mt][3],
                      sA + ((64 * wr + 16 * mt + lrow) * AST + kt * 16 + lcol) * 2);
#pragma unroll
            for (int np = 0; np < 2; np++) {
                uint32_t b0, b1, b2, b3;
                ldsm4t(b0, b1, b2, b3,
                       sW + ((16 * kt + lrow) * WST + 32 * wc + np * 16 + lcol) * 2);
#pragma unroll
                for (int mt = 0; mt < 4; mt++) {
                    mma_f16(acc[mt][2 * np],     af[mt][0], af[mt][1], af[mt][2], af[mt][3], b0, b1);
                    mma_f16(acc[mt][2 * np + 1], af[mt][0], af[mt][1], af[mt][2], af[mt][3], b2, b3);
                }
            }
        }
    }

#pragma unroll
    for (int mt = 0; mt < 4; mt++) {
        int row = row0 + 64 * wr + 16 * mt + r;
#pragma unroll
        for (int nt = 0; nt < 4; nt++) {
            int col = col0 + 32 * wc + 8 * nt + 2 * tg;
            float b0 = bias[col], b1 = bias[col + 1];
            __half2 h0 = __floats2half2_rn((acc[mt][nt][0] + b0) * oscale,
                                           (acc[mt][nt][1] + b1) * oscale);
            __half2 h1 = __floats2half2_rn((acc[mt][nt][2] + b0) * oscale,
                                           (acc[mt][nt][3] + b1) * oscale);
            *(__half2*)(C + (size_t)row * Hdim + col) = h0;
            *(__half2*)(C + (size_t)(row + 8) * Hdim + col) = h1;
        }
    }
}

// ---------------- flash attention (mma-based row sums) ----------------------
// CTA: 128 queries, 256 threads / 8 warps. Warp (wr = w&3, wc = w>>2):
//  S phase:  rows 32*wr..+31, keys 32*wc..+31 of a 64-key tile, K=256.
//  P 128x64 fp16 via smem (pad 72); P handoff uses a NAMED 64-thread barrier.
//  PV phase: rows 32*wr..+31, H cols 128*wc..+127, K = all 64 keys.
//  Row sums l computed by 2 extra mma/pk with a ones-B fragment, accumulating
//  the SAME fp16 P values used for PV (no shuffles, no smem merge).
// Pipeline per tile: CP_WAIT(0) -> sync -> prefetch(j+1) -> compute(j); WAR-safe.
// O normalized in-kernel, written fp16 to [bt][n][h] layout.
#define QST3 264
#define TILEB (64*QST3*2)               /* 33792 */
#define SM3_Q 0
#define SM3_K (128*QST3*2)              /* 67584 */
#define SM3_V (SM3_K + 2*TILEB)         /* 135168 */
#define SM3_P (SM3_V + 2*TILEB)         /* 202752 */
#define PST3 72
#define ATT3_SMEM (SM3_P + 128*PST3*2)  /* 221184 */

__global__ __launch_bounds__(256, 1) void attn_kernel() {
    extern __shared__ char smc[];
    uint32_t sb = smem_u32(smc);
    int tid = threadIdx.x;
    int w = tid >> 5, lane = tid & 31;
    int r = lane >> 2, tg = lane & 3;
    int lrow = (lane & 7) + ((lane >> 3) & 1) * 8;
    int lcol = ((lane >> 4) & 1) * 8;
    int wr = w & 3, wc = w >> 2;
    const uint32_t ONES = 0x3C003C00u;   // half2(1.0, 1.0)

    int qt = blockIdx.x, b = blockIdx.y, n = blockIdx.z;
    size_t rowbase = ((size_t)n * Bdim + b) * Tdim;
    const __half* Qg = g_q + (rowbase + (size_t)qt * 128) * Hdim;
    const __half* Kg0 = g_k + rowbase * Hdim;
    const __half* Vg0 = g_v + rowbase * Hdim;

    // ---- Q + K/V tile 0 ----
#pragma unroll
    for (int i = tid; i < 4096; i += 256) {
        int rr = i >> 5, seg = i & 31;
        cp16(sb + SM3_Q + (rr * QST3 + seg * 8) * 2, Qg + rr * 256 + seg * 8);
    }
#pragma unroll
    for (int i = tid; i < 2048; i += 256) {
        int rr = i >> 5, seg = i & 31;
        cp16(sb + SM3_K + (rr * QST3 + seg * 8) * 2, Kg0 + rr * 256 + seg * 8);
        cp16(sb + SM3_V + (rr * QST3 + seg * 8) * 2, Vg0 + rr * 256 + seg * 8);
    }
    CP_COMMIT();

    float oacc[2][16][4];
#pragma unroll
    for (int g = 0; g < 2; g++)
#pragma unroll
        for (int i = 0; i < 16; i++)
#pragma unroll
            for (int j = 0; j < 4; j++) oacc[g][i][j] = 0.f;
    float lsum[2][4];
#pragma unroll
    for (int g = 0; g < 2; g++)
#pragma unroll
        for (int j = 0; j < 4; j++) lsum[g][j] = 0.f;

    for (int j = 0; j < 16; j++) {
        CP_WAIT(0);        // tile j landed
        __syncthreads();   // publish tile j; compute(j-1) done (WAR-safe)
        if (j + 1 < 16) {
            int nb = (j + 1) & 1;
            const __half* Kg = Kg0 + (size_t)(j + 1) * 64 * 256;
            const __half* Vg = Vg0 + (size_t)(j + 1) * 64 * 256;
#pragma unroll
            for (int i = tid; i < 2048; i += 256) {
                int rr = i >> 5, seg = i & 31;
                cp16(sb + SM3_K + nb * TILEB + (rr * QST3 + seg * 8) * 2,
                     Kg + rr * 256 + seg * 8);
                cp16(sb + SM3_V + nb * TILEB + (rr * QST3 + seg * 8) * 2,
                     Vg + rr * 256 + seg * 8);
            }
            CP_COMMIT();
        }

        uint32_t kbuf = sb + SM3_K + (j & 1) * TILEB;
        uint32_t vbuf = sb + SM3_V + (j & 1) * TILEB;

        // ---- S = Q K^T : warp 32 rows x 32 keys, K=256 ----
        float sacc[2][4][4];
#pragma unroll
        for (int g = 0; g < 2; g++)
#pragma unroll
            for (int i = 0; i < 4; i++)
#pragma unroll
                for (int jj = 0; jj < 4; jj++) sacc[g][i][jj] = 0.f;

#pragma unroll
        for (int c = 0; c < 16; c++) {
            int k0 = c * 16;
            uint32_t q0[4], q1[4];
            ldsm4(q0[0], q0[1], q0[2], q0[3],
                  sb + SM3_Q + ((32 * wr + lrow) * QST3 + k0 + lcol) * 2);
            ldsm4(q1[0], q1[1], q1[2], q1[3],
                  sb + SM3_Q + ((32 * wr + 16 + lrow) * QST3 + k0 + lcol) * 2);
#pragma unroll
            for (int kg = 0; kg < 2; kg++) {
                uint32_t b0, b1, b2, b3;
                ldsm4(b0, b1, b2, b3,
                      kbuf + ((32 * wc + 16 * kg + lrow) * QST3 + k0 + lcol) * 2);
                mma_f16(sacc[0][2 * kg],     q0[0], q0[1], q0[2], q0[3], b0, b2);
                mma_f16(sacc[0][2 * kg + 1], q0[0], q0[1], q0[2], q0[3], b1, b3);
                mma_f16(sacc[1][2 * kg],     q1[0], q1[1], q1[2], q1[3], b0, b2);
                mma_f16(sacc[1][2 * kg + 1], q1[0], q1[1], q1[2], q1[3], b1, b3);
            }
        }

        // ---- softmax: P = 2^S -> smem (row sums deferred to PV-side mma) ---
#pragma unroll
        for (int g = 0; g < 2; g++) {
            int row0 = 32 * wr + 16 * g + r;
#pragma unroll
            for (int nt = 0; nt < 4; nt++) {
                float e0 = ex2(sacc[g][nt][0]);
                float e1 = ex2(sacc[g][nt][1]);
                float e2 = ex2(sacc[g][nt][2]);
                float e3 = ex2(sacc[g][nt][3]);
                int col = 32 * wc + 8 * nt + 2 * tg;
                *(__half2*)(smc + SM3_P + (row0 * PST3 + col) * 2) =
                    __floats2half2_rn(e0, e1);
                *(__half2*)(smc + SM3_P + ((row0 + 8) * PST3 + col) * 2) =
                    __floats2half2_rn(e2, e3);
            }
        }
        // named 64-thread barrier: P rows owned by pair {wr, wr+4}
        asm volatile("bar.sync %0, 64;" :: "r"(wr + 1) : "memory");

        // ---- O += P V (+ l += P·1) : warp 32 rows x 128 H, K = 64 keys ----
#pragma unroll
        for (int pk = 0; pk < 4; pk++) {
            uint32_t pf0[4], pf1[4];
            ldsm4(pf0[0], pf0[1], pf0[2], pf0[3],
                  sb + SM3_P + ((32 * wr + lrow) * PST3 + 16 * pk + lcol) * 2);
            ldsm4(pf1[0], pf1[1], pf1[2], pf1[3],
                  sb + SM3_P + ((32 * wr + 16 + lrow) * PST3 + 16 * pk + lcol) * 2);
            mma_f16(lsum[0], pf0[0], pf0[1], pf0[2], pf0[3], ONES, ONES);
            mma_f16(lsum[1], pf1[0], pf1[1], pf1[2], pf1[3], ONES, ONES);
#pragma unroll
            for (int hg = 0; hg < 8; hg++) {
                uint32_t v0, v1, v2, v3;
                ldsm4t(v0, v1, v2, v3,
                       vbuf + ((16 * pk + lrow) * QST3 + 128 * wc + 16 * hg + lcol) * 2);
                mma_f16(oacc[0][2 * hg],     pf0[0], pf0[1], pf0[2], pf0[3], v0, v1);
                mma_f16(oacc[0][2 * hg + 1], pf0[0], pf0[1], pf0[2], pf0[3], v2, v3);
                mma_f16(oacc[1][2 * hg],     pf1[0], pf1[1], pf1[2], pf1[3], v0, v1);
                mma_f16(oacc[1][2 * hg + 1], pf1[0], pf1[1], pf1[2], pf1[3], v2, v3);
            }
        }
    }

    // ---- normalize (per-warp row sums from lsum), write fp16 [bt][n][h] ----
    size_t btbase = (size_t)b * Tdim + (size_t)qt * 128;   // global bt of row 0
#pragma unroll
    for (int g = 0; g < 2; g++) {
        int row0 = 32 * wr + 16 * g + r;
        float inv0 = 1.f / lsum[g][0];     // row row0 sum (all 1024 keys)
        float inv1 = 1.f / lsum[g][2];     // row row0+8 sum
        __half* Og  = g_oh + ((btbase + row0) * NBR + n) * Hdim;
        __half* Og8 = g_oh + ((btbase + row0 + 8) * NBR + n) * Hdim;
#pragma unroll
        for (int nt = 0; nt < 16; nt++) {
            int col = 128 * wc + 8 * nt + 2 * tg;
            *(__half2*)(Og + col)  = __floats2half2_rn(oacc[g][nt][0] * inv0,
                                                       oacc[g][nt][1] * inv0);
            *(__half2*)(Og8 + col) = __floats2half2_rn(oacc[g][nt][2] * inv1,
                                                       oacc[g][nt][3] * inv1);
        }
    }
}

// ---------------- combine branches + LN over H, write output ----------------
__global__ void ln2_kernel(const float* __restrict__ w2,
                           const float* __restrict__ b2,
                           float* __restrict__ out) {
    int bt = blockIdx.x, h = threadIdx.x;
    const __half* ob = g_oh + (size_t)bt * NBR * Hdim;
    float o0 = __half2float(ob[h]);
    float o1 = __half2float(ob[Hdim + h]);
    float o2 = __half2float(ob[2 * Hdim + h]);
    float o3 = __half2float(ob[3 * Hdim + h]);
    float o4 = __half2float(ob[4 * Hdim + h]);
    float o5 = __half2float(ob[5 * Hdim + h]);
    float o6 = __half2float(ob[6 * Hdim + h]);
    float o7 = __half2float(ob[7 * Hdim + h]);
    float rc = o0 - o1 - o2 - o3;
    float ic = o4 + o5 + o6 - o7;
    float v[4] = {rc, rc * rc, ic, ic * ic};
    block_reduce_sum4(v);
    const float invH = 1.f / (float)Hdim;
    float mr = v[0] * invH, vr = v[1] * invH - mr * mr;
    float mi = v[2] * invH, vi = v[3] * invH - mi * mi;
    float wr = w2[h], br = b2[h];
    float2 ov;
    ov.x = (rc - mr) * rsqrtf(vr + EPSV) * wr + br;
    ov.y = (ic - mi) * rsqrtf(vi + EPSV) * wr + br;
    ((float2*)out)[(size_t)bt * Hdim + h] = ov;
}

// ---------------- launch ----------------------------------------------------
extern "C" void kernel_launch(void* const* d_in, const int* in_sizes, int n_in,
                              void* d_out, int out_size) {
    const float* x    = (const float*)d_in[0];
    const float* Wq   = (const float*)d_in[1];
    const float* bq   = (const float*)d_in[2];
    const float* Wk   = (const float*)d_in[3];
    const float* bk   = (const float*)d_in[4];
    const float* Wv   = (const float*)d_in[5];
    const float* bv   = (const float*)d_in[6];
    const float* ln1w = (const float*)d_in[7];
    const float* ln1b = (const float*)d_in[8];
    const float* ln2w = (const float*)d_in[9];
    const float* ln2b = (const float*)d_in[10];
    float* out = (float*)d_out;

    ln1_wcvt_kernel<<<LN1_BLOCKS + 512, 256>>>(x, ln1w, ln1b, Wq, Wk, Wv);

    cudaFuncSetAttribute(qkv_gemm_kernel, cudaFuncAttributeMaxDynamicSharedMemorySize,
                         GEMM2_SMEM);
    qkv_gemm_kernel<<<dim3(BT / 128, Hdim / 128, 24), 256, GEMM2_SMEM>>>(bq, bk, bv);

    cudaFuncSetAttribute(attn_kernel, cudaFuncAttributeMaxDynamicSharedMemorySize,
                         ATT3_SMEM);
    attn_kernel<<<dim3(Tdim / 128, Bdim, NBR), 256, ATT3_SMEM>>>();

    ln2_kernel<<<BT, Hdim>>>(ln2w, ln2b, out);
}

// round 17
// speedup vs baseline: 1.0720x; 1.0110x over previous
#include <cuda_runtime.h>
#include <cuda_fp16.h>
#include <math.h>
#include <stdint.h>

#define Bdim 8
#define Tdim 1024
#define Fdim 256
#define Hdim 256
#define BT (Bdim*Tdim)          /* 8192 */
#define NBR 8
#define EPSV 1e-5f

// ---------------- scratch (static device globals; no allocations) -----------
__device__ __half g_real[(size_t)BT*Fdim];
__device__ __half g_imag[(size_t)BT*Fdim];
__device__ __half g_whq[(size_t)NBR*Fdim*Hdim];
__device__ __half g_whk[(size_t)NBR*Fdim*Hdim];
__device__ __half g_whv[(size_t)NBR*Fdim*Hdim];
__device__ __half g_q[(size_t)NBR*BT*Hdim];
__device__ __half g_k[(size_t)NBR*BT*Hdim];
__device__ __half g_v[(size_t)NBR*BT*Hdim];
__device__ __half g_oh[(size_t)NBR*BT*Hdim];   // normalized O, fp16, [bt][n][h]

// ---------------- helpers ----------------------------------------------------
__device__ __forceinline__ float ex2(float x) {
    float y;
    asm("ex2.approx.ftz.f32 %0, %1;" : "=f"(y) : "f"(x));
    return y;
}

__device__ __forceinline__ uint32_t smem_u32(const void* p) {
    uint32_t a;
    asm("{ .reg .u64 t; cvta.to.shared.u64 t, %1; cvt.u32.u64 %0, t; }"
        : "=r"(a) : "l"(p));
    return a;
}

__device__ __forceinline__ void mma_f16(float* d,
                                        uint32_t a0, uint32_t a1, uint32_t a2, uint32_t a3,
                                        uint32_t b0, uint32_t b1) {
    asm volatile(
        "mma.sync.aligned.m16n8k16.row.col.f32.f16.f16.f32 "
        "{%0,%1,%2,%3}, {%4,%5,%6,%7}, {%8,%9}, {%0,%1,%2,%3};"
        : "+f"(d[0]), "+f"(d[1]), "+f"(d[2]), "+f"(d[3])
        : "r"(a0), "r"(a1), "r"(a2), "r"(a3), "r"(b0), "r"(b1));
}

__device__ __forceinline__ void ldsm4(uint32_t& r0, uint32_t& r1, uint32_t& r2, uint32_t& r3,
                                      uint32_t a) {
    asm volatile("ldmatrix.sync.aligned.m8n8.x4.shared.b16 {%0,%1,%2,%3}, [%4];"
                 : "=r"(r0), "=r"(r1), "=r"(r2), "=r"(r3) : "r"(a));
}
__device__ __forceinline__ void ldsm4t(uint32_t& r0, uint32_t& r1, uint32_t& r2, uint32_t& r3,
                                       uint32_t a) {
    asm volatile("ldmatrix.sync.aligned.m8n8.x4.trans.shared.b16 {%0,%1,%2,%3}, [%4];"
                 : "=r"(r0), "=r"(r1), "=r"(r2), "=r"(r3) : "r"(a));
}

__device__ __forceinline__ void cp16(uint32_t dst, const void* src) {
    asm volatile("cp.async.cg.shared.global [%0], [%1], 16;" :: "r"(dst), "l"(src));
}
#define CP_COMMIT() asm volatile("cp.async.commit_group;" ::: "memory")
#define CP_WAIT(n)  asm volatile("cp.async.wait_group %0;" :: "n"(n) : "memory")

__device__ __forceinline__ uint32_t h2u(__half2 h) {
    return *reinterpret_cast<uint32_t*>(&h);
}

// ---------------- block reduction of 4 values (256 threads) -----------------
__device__ __forceinline__ void block_reduce_sum4(float v[4]) {
    __shared__ float buf[8][4];
    int lane = threadIdx.x & 31, wp = threadIdx.x >> 5;
#pragma unroll
    for (int k = 0; k < 4; k++) {
#pragma unroll
        for (int o = 16; o > 0; o >>= 1)
            v[k] += __shfl_xor_sync(0xffffffffu, v[k], o);
    }
    if (lane == 0) {
        buf[wp][0] = v[0]; buf[wp][1] = v[1]; buf[wp][2] = v[2]; buf[wp][3] = v[3];
    }
    __syncthreads();
#pragma unroll
    for (int k = 0; k < 4; k++) {
        float t = 0.f;
#pragma unroll
        for (int w = 0; w < 8; w++) t += buf[w][k];
        v[k] = t;
    }
}

// ---------------- fused: warp-per-row LN over F + W fp32->fp16 --------------
#define LN1_BLOCKS (BT / 8)   /* 1024: 8 rows per 256-thread block */
__global__ void ln1_wcvt_kernel(const float* __restrict__ x,
                                const float* __restrict__ w,
                                const float* __restrict__ b,
                                const float* __restrict__ Wq,
                                const float* __restrict__ Wk,
                                const float* __restrict__ Wv) {
    if (blockIdx.x >= LN1_BLOCKS) {
        int i = ((blockIdx.x - LN1_BLOCKS) * 256 + threadIdx.x) * 4;
        float4 a = *(const float4*)(Wq + i);
        float4 bb = *(const float4*)(Wk + i);
        float4 c = *(const float4*)(Wv + i);
        *(uint2*)(g_whq + i) = make_uint2(h2u(__floats2half2_rn(a.x, a.y)),
                                          h2u(__floats2half2_rn(a.z, a.w)));
        *(uint2*)(g_whk + i) = make_uint2(h2u(__floats2half2_rn(bb.x, bb.y)),
                                          h2u(__floats2half2_rn(bb.z, bb.w)));
        *(uint2*)(g_whv + i) = make_uint2(h2u(__floats2half2_rn(c.x, c.y)),
                                          h2u(__floats2half2_rn(c.z, c.w)));
        return;
    }
    int bt = blockIdx.x * 8 + (threadIdx.x >> 5);
    int lane = threadIdx.x & 31;
    const float2* xr = (const float2*)x + (size_t)bt * Fdim;

    float2 xv[8];
    float sr = 0.f, sr2 = 0.f, si = 0.f, si2 = 0.f;
#pragma unroll
    for (int k = 0; k < 8; k++) {
        xv[k] = xr[lane + 32 * k];
        sr += xv[k].x; sr2 += xv[k].x * xv[k].x;
        si += xv[k].y; si2 += xv[k].y * xv[k].y;
    }
#pragma unroll
    for (int o = 16; o > 0; o >>= 1) {
        sr  += __shfl_xor_sync(0xffffffffu, sr, o);
        sr2 += __shfl_xor_sync(0xffffffffu, sr2, o);
        si  += __shfl_xor_sync(0xffffffffu, si, o);
        si2 += __shfl_xor_sync(0xffffffffu, si2, o);
    }
    const float invF = 1.f / (float)Fdim;
    float mr = sr * invF, rr = rsqrtf(sr2 * invF - mr * mr + EPSV);
    float mi = si * invF, ri = rsqrtf(si2 * invF - mi * mi + EPSV);
#pragma unroll
    for (int k = 0; k < 8; k++) {
        int f = lane + 32 * k;
        float wf = w[f], bf = b[f];
        g_real[(size_t)bt * Fdim + f] = __float2half_rn((xv[k].x - mr) * rr * wf + bf);
        g_imag[(size_t)bt * Fdim + f] = __float2half_rn((xv[k].y - mi) * ri * wf + bf);
    }
}

// ---------------- batched QKV projection GEMM (double-buffered, safe) -------
#define AST 72
#define WST 136
#define ABUF (128*AST*2)     /* 18432 */
#define WBUF (64*WST*2)      /* 17408 */
#define GEMM2_SMEM (2*ABUF + 2*WBUF)   /* 71680 */
#define SC2 (0.0625f * 1.44269504f)

__global__ __launch_bounds__(256, 2) void qkv_gemm_kernel(
    const float* __restrict__ bq, const float* __restrict__ bk,
    const float* __restrict__ bv) {
    extern __shared__ char sgc[];
    uint32_t sb = smem_u32(sgc);

    int op = blockIdx.z;
    int n = op / 3, which = op - n * 3;
    int plane;
    const __half* Wh; const float* bias; __half* C;
    if (which == 0)      { plane = (n >> 1) & 1;  Wh = g_whq + (size_t)n * Fdim * Hdim; bias = bq + n * Hdim; C = g_q + (size_t)n * BT * Hdim; }
    else if (which == 1) { plane = n & 1;         Wh = g_whk + (size_t)n * Fdim * Hdim; bias = bk + n * Hdim; C = g_k + (size_t)n * BT * Hdim; }
    else                 { plane = __popc(n) & 1; Wh = g_whv + (size_t)n * Fdim * Hdim; bias = bv + n * Hdim; C = g_v + (size_t)n * BT * Hdim; }
    const __half* A = plane ? g_imag : g_real;
    const float oscale = (which == 0) ? SC2 : 1.0f;

    int row0 = blockIdx.x * 128, col0 = blockIdx.y * 128;
    int tid = threadIdx.x;
    int w = tid >> 5, lane = tid & 31;
    int r = lane >> 2, tg = lane & 3;
    int wr = w & 1, wc = w >> 1;
    int lrow = (lane & 7) + ((lane >> 3) & 1) * 8;
    int lcol = ((lane >> 4) & 1) * 8;

    float acc[4][4][4];
#pragma unroll
    for (int mt = 0; mt < 4; mt++)
#pragma unroll
        for (int nt = 0; nt < 4; nt++)
#pragma unroll
            for (int j = 0; j < 4; j++) acc[mt][nt][j] = 0.f;

    // prefetch chunk 0 into buffer 0
#pragma unroll
    for (int i = tid; i < 1024; i += 256) {
        int rr = i >> 3, seg = i & 7;
        cp16(sb + (rr * AST + seg * 8) * 2,
             A + (size_t)(row0 + rr) * Fdim + seg * 8);
    }
#pragma unroll
    for (int i = tid; i < 1024; i += 256) {
        int rr = i >> 4, seg = i & 15;
        cp16(sb + 2 * ABUF + (rr * WST + seg * 8) * 2,
             Wh + (size_t)rr * Hdim + col0 + seg * 8);
    }
    CP_COMMIT();

    for (int kc = 0; kc < 4; kc++) {
        CP_WAIT(0);
        __syncthreads();   // publish chunk kc; compute(kc-1) done (WAR-safe)
        if (kc < 3) {
            int nb = (kc + 1) & 1;
            int k0 = (kc + 1) * 64;
#pragma unroll
            for (int i = tid; i < 1024; i += 256) {
                int rr = i >> 3, seg = i & 7;
                cp16(sb + nb * ABUF + (rr * AST + seg * 8) * 2,
                     A + (size_t)(row0 + rr) * Fdim + k0 + seg * 8);
            }
#pragma unroll
            for (int i = tid; i < 1024; i += 256) {
                int rr = i >> 4, seg = i & 15;
                cp16(sb + 2 * ABUF + nb * WBUF + (rr * WST + seg * 8) * 2,
                     Wh + (size_t)(k0 + rr) * Hdim + col0 + seg * 8);
            }
            CP_COMMIT();
        }

        uint32_t sA = sb + (kc & 1) * ABUF;
        uint32_t sW = sb + 2 * ABUF + (kc & 1) * WBUF;
#pragma unroll
        for (int kt = 0; kt < 4; kt++) {
            uint32_t af[4][4];
#pragma unroll
            for (int mt = 0; mt < 4; mt++)
                ldsm4(af[mt][0], af[mt][1], af[mt][2], af[mt][3],
                      sA + ((64 * wr + 16 * mt + lrow) * AST + kt * 16 + lcol) * 2);
#pragma unroll
            for (int np = 0; np < 2; np++) {
                uint32_t b0, b1, b2, b3;
                ldsm4t(b0, b1, b2, b3,
                       sW + ((16 * kt + lrow) * WST + 32 * wc + np * 16 + lcol) * 2);
#pragma unroll
                for (int mt = 0; mt < 4; mt++) {
                    mma_f16(acc[mt][2 * np],     af[mt][0], af[mt][1], af[mt][2], af[mt][3], b0, b1);
                    mma_f16(acc[mt][2 * np + 1], af[mt][0], af[mt][1], af[mt][2], af[mt][3], b2, b3);
                }
            }
        }
    }

#pragma unroll
    for (int mt = 0; mt < 4; mt++) {
        int row = row0 + 64 * wr + 16 * mt + r;
#pragma unroll
        for (int nt = 0; nt < 4; nt++) {
            int col = col0 + 32 * wc + 8 * nt + 2 * tg;
            float b0 = bias[col], b1 = bias[col + 1];
            __half2 h0 = __floats2half2_rn((acc[mt][nt][0] + b0) * oscale,
                                           (acc[mt][nt][1] + b1) * oscale);
            __half2 h1 = __floats2half2_rn((acc[mt][nt][2] + b0) * oscale,
                                           (acc[mt][nt][3] + b1) * oscale);
            *(__half2*)(C + (size_t)row * Hdim + col) = h0;
            *(__half2*)(C + (size_t)(row + 8) * Hdim + col) = h1;
        }
    }
}

// ---------------- flash attention (register-P for own keys) -----------------
// CTA: 128 queries, 256 threads / 8 warps. Warp (wr = w&3, wc = w>>2):
//  S phase:  rows 32*wr..+31, keys 32*wc..+31 of a 64-key tile, K=256.
//  P 128x64 fp16 via smem (pad 72); the warp's OWN 32-key P half stays in
//  registers (S output frags == PV A frags), only the partner half is ldsm'd.
//  PV phase: rows 32*wr..+31, H cols 128*wc..+127, K = all 64 keys.
//  Row sums via 2 extra mma/pk with ones-B (same fp16 P as PV).
// Pipeline per tile: CP_WAIT(0) -> sync -> prefetch(j+1) -> compute(j); WAR-safe.
// O normalized in-kernel, written fp16 to [bt][n][h] layout.
#define QST3 264
#define TILEB (64*QST3*2)               /* 33792 */
#define SM3_Q 0
#define SM3_K (128*QST3*2)              /* 67584 */
#define SM3_V (SM3_K + 2*TILEB)         /* 135168 */
#define SM3_P (SM3_V + 2*TILEB)         /* 202752 */
#define PST3 72
#define ATT3_SMEM (SM3_P + 128*PST3*2)  /* 221184 */

__global__ __launch_bounds__(256, 1) void attn_kernel() {
    extern __shared__ char smc[];
    uint32_t sb = smem_u32(smc);
    int tid = threadIdx.x;
    int w = tid >> 5, lane = tid & 31;
    int r = lane >> 2, tg = lane & 3;
    int lrow = (lane & 7) + ((lane >> 3) & 1) * 8;
    int lcol = ((lane >> 4) & 1) * 8;
    int wr = w & 3, wc = w >> 2;
    const uint32_t ONES = 0x3C003C00u;   // half2(1.0, 1.0)

    int qt = blockIdx.x, b = blockIdx.y, n = blockIdx.z;
    size_t rowbase = ((size_t)n * Bdim + b) * Tdim;
    const __half* Qg = g_q + (rowbase + (size_t)qt * 128) * Hdim;
    const __half* Kg0 = g_k + rowbase * Hdim;
    const __half* Vg0 = g_v + rowbase * Hdim;

    // ---- Q + K/V tile 0 ----
#pragma unroll
    for (int i = tid; i < 4096; i += 256) {
        int rr = i >> 5, seg = i & 31;
        cp16(sb + SM3_Q + (rr * QST3 + seg * 8) * 2, Qg + rr * 256 + seg * 8);
    }
#pragma unroll
    for (int i = tid; i < 2048; i += 256) {
        int rr = i >> 5, seg = i & 31;
        cp16(sb + SM3_K + (rr * QST3 + seg * 8) * 2, Kg0 + rr * 256 + seg * 8);
        cp16(sb + SM3_V + (rr * QST3 + seg * 8) * 2, Vg0 + rr * 256 + seg * 8);
    }
    CP_COMMIT();

    float oacc[2][16][4];
#pragma unroll
    for (int g = 0; g < 2; g++)
#pragma unroll
        for (int i = 0; i < 16; i++)
#pragma unroll
            for (int j = 0; j < 4; j++) oacc[g][i][j] = 0.f;
    float lsum[2][4];
#pragma unroll
    for (int g = 0; g < 2; g++)
#pragma unroll
        for (int j = 0; j < 4; j++) lsum[g][j] = 0.f;

    for (int j = 0; j < 16; j++) {
        CP_WAIT(0);        // tile j landed
        __syncthreads();   // publish tile j; compute(j-1) done (WAR-safe)
        if (j + 1 < 16) {
            int nb = (j + 1) & 1;
            const __half* Kg = Kg0 + (size_t)(j + 1) * 64 * 256;
            const __half* Vg = Vg0 + (size_t)(j + 1) * 64 * 256;
#pragma unroll
            for (int i = tid; i < 2048; i += 256) {
                int rr = i >> 5, seg = i & 31;
                cp16(sb + SM3_K + nb * TILEB + (rr * QST3 + seg * 8) * 2,
                     Kg + rr * 256 + seg * 8);
                cp16(sb + SM3_V + nb * TILEB + (rr * QST3 + seg * 8) * 2,
                     Vg + rr * 256 + seg * 8);
            }
            CP_COMMIT();
        }

        uint32_t kbuf = sb + SM3_K + (j & 1) * TILEB;
        uint32_t vbuf = sb + SM3_V + (j & 1) * TILEB;

        // ---- S = Q K^T : warp 32 rows x 32 keys, K=256 ----
        float sacc[2][4][4];
#pragma unroll
        for (int g = 0; g < 2; g++)
#pragma unroll
            for (int i = 0; i < 4; i++)
#pragma unroll
                for (int jj = 0; jj < 4; jj++) sacc[g][i][jj] = 0.f;

#pragma unroll
        for (int c = 0; c < 16; c++) {
            int k0 = c * 16;
            uint32_t q0[4], q1[4];
            ldsm4(q0[0], q0[1], q0[2], q0[3],
                  sb + SM3_Q + ((32 * wr + lrow) * QST3 + k0 + lcol) * 2);
            ldsm4(q1[0], q1[1], q1[2], q1[3],
                  sb + SM3_Q + ((32 * wr + 16 + lrow) * QST3 + k0 + lcol) * 2);
#pragma unroll
            for (int kg = 0; kg < 2; kg++) {
                uint32_t b0, b1, b2, b3;
                ldsm4(b0, b1, b2, b3,
                      kbuf + ((32 * wc + 16 * kg + lrow) * QST3 + k0 + lcol) * 2);
                mma_f16(sacc[0][2 * kg],     q0[0], q0[1], q0[2], q0[3], b0, b2);
                mma_f16(sacc[0][2 * kg + 1], q0[0], q0[1], q0[2], q0[3], b1, b3);
                mma_f16(sacc[1][2 * kg],     q1[0], q1[1], q1[2], q1[3], b0, b2);
                mma_f16(sacc[1][2 * kg + 1], q1[0], q1[1], q1[2], q1[3], b1, b3);
            }
        }

        // ---- softmax: P = 2^S -> smem AND registers (own half) -------------
        uint32_t pH[2][4][2];   // [g][nt][h01/h23] — warp's own 32-key P frags
#pragma unroll
        for (int g = 0; g < 2; g++) {
            int row0 = 32 * wr + 16 * g + r;
#pragma unroll
            for (int nt = 0; nt < 4; nt++) {
                float e0 = ex2(sacc[g][nt][0]);
                float e1 = ex2(sacc[g][nt][1]);
                float e2 = ex2(sacc[g][nt][2]);
                float e3 = ex2(sacc[g][nt][3]);
                __half2 h01 = __floats2half2_rn(e0, e1);
                __half2 h23 = __floats2half2_rn(e2, e3);
                pH[g][nt][0] = h2u(h01);
                pH[g][nt][1] = h2u(h23);
                int col = 32 * wc + 8 * nt + 2 * tg;
                *(__half2*)(smc + SM3_P + (row0 * PST3 + col) * 2) = h01;
                *(__half2*)(smc + SM3_P + ((row0 + 8) * PST3 + col) * 2) = h23;
            }
        }
        // named 64-thread barrier: P rows owned by pair {wr, wr+4}
        asm volatile("bar.sync %0, 64;" :: "r"(wr + 1) : "memory");

        // ---- O += P V (+ l += P·1) : warp 32 rows x 128 H, K = 64 keys ----
#pragma unroll
        for (int pk = 0; pk < 4; pk++) {
            uint32_t pf0[4], pf1[4];
            if ((pk >> 1) == wc) {
                // own key chunk: fragments straight from registers
                int kg = pk & 1;
                pf0[0] = pH[0][2 * kg][0];     pf0[1] = pH[0][2 * kg][1];
                pf0[2] = pH[0][2 * kg + 1][0]; pf0[3] = pH[0][2 * kg + 1][1];
                pf1[0] = pH[1][2 * kg][0];     pf1[1] = pH[1][2 * kg][1];
                pf1[2] = pH[1][2 * kg + 1][0]; pf1[3] = pH[1][2 * kg + 1][1];
            } else {
                ldsm4(pf0[0], pf0[1], pf0[2], pf0[3],
                      sb + SM3_P + ((32 * wr + lrow) * PST3 + 16 * pk + lcol) * 2);
                ldsm4(pf1[0], pf1[1], pf1[2], pf1[3],
                      sb + SM3_P + ((32 * wr + 16 + lrow) * PST3 + 16 * pk + lcol) * 2);
            }
            mma_f16(lsum[0], pf0[0], pf0[1], pf0[2], pf0[3], ONES, ONES);
            mma_f16(lsum[1], pf1[0], pf1[1], pf1[2], pf1[3], ONES, ONES);
#pragma unroll
            for (int hg = 0; hg < 8; hg++) {
                uint32_t v0, v1, v2, v3;
                ldsm4t(v0, v1, v2, v3,
                       vbuf + ((16 * pk + lrow) * QST3 + 128 * wc + 16 * hg + lcol) * 2);
                mma_f16(oacc[0][2 * hg],     pf0[0], pf0[1], pf0[2], pf0[3], v0, v1);
                mma_f16(oacc[0][2 * hg + 1], pf0[0], pf0[1], pf0[2], pf0[3], v2, v3);
                mma_f16(oacc[1][2 * hg],     pf1[0], pf1[1], pf1[2], pf1[3], v0, v1);
                mma_f16(oacc[1][2 * hg + 1], pf1[0], pf1[1], pf1[2], pf1[3], v2, v3);
            }
        }
    }

    // ---- normalize (per-warp row sums from lsum), write fp16 [bt][n][h] ----
    size_t btbase = (size_t)b * Tdim + (size_t)qt * 128;   // global bt of row 0
#pragma unroll
    for (int g = 0; g < 2; g++) {
        int row0 = 32 * wr + 16 * g + r;
        float inv0 = 1.f / lsum[g][0];     // row row0 sum (all 1024 keys)
        float inv1 = 1.f / lsum[g][2];     // row row0+8 sum
        __half* Og  = g_oh + ((btbase + row0) * NBR + n) * Hdim;
        __half* Og8 = g_oh + ((btbase + row0 + 8) * NBR + n) * Hdim;
#pragma unroll
        for (int nt = 0; nt < 16; nt++) {
            int col = 128 * wc + 8 * nt + 2 * tg;
            *(__half2*)(Og + col)  = __floats2half2_rn(oacc[g][nt][0] * inv0,
                                                       oacc[g][nt][1] * inv0);
            *(__half2*)(Og8 + col) = __floats2half2_rn(oacc[g][nt][2] * inv1,
                                                       oacc[g][nt][3] * inv1);
        }
    }
}

// ---------------- combine branches + LN over H, write output ----------------
__global__ void ln2_kernel(const float* __restrict__ w2,
                           const float* __restrict__ b2,
                           float* __restrict__ out) {
    int bt = blockIdx.x, h = threadIdx.x;
    const __half* ob = g_oh + (size_t)bt * NBR * Hdim;
    float o0 = __half2float(ob[h]);
    float o1 = __half2float(ob[Hdim + h]);
    float o2 = __half2float(ob[2 * Hdim + h]);
    float o3 = __half2float(ob[3 * Hdim + h]);
    float o4 = __half2float(ob[4 * Hdim + h]);
    float o5 = __half2float(ob[5 * Hdim + h]);
    float o6 = __half2float(ob[6 * Hdim + h]);
    float o7 = __half2float(ob[7 * Hdim + h]);
    float rc = o0 - o1 - o2 - o3;
    float ic = o4 + o5 + o6 - o7;
    float v[4] = {rc, rc * rc, ic, ic * ic};
    block_reduce_sum4(v);
    const float invH = 1.f / (float)Hdim;
    float mr = v[0] * invH, vr = v[1] * invH - mr * mr;
    float mi = v[2] * invH, vi = v[3] * invH - mi * mi;
    float wr = w2[h], br = b2[h];
    float2 ov;
    ov.x = (rc - mr) * rsqrtf(vr + EPSV) * wr + br;
    ov.y = (ic - mi) * rsqrtf(vi + EPSV) * wr + br;
    ((float2*)out)[(size_t)bt * Hdim + h] = ov;
}

// ---------------- launch ----------------------------------------------------
extern "C" void kernel_launch(void* const* d_in, const int* in_sizes, int n_in,
                              void* d_out, int out_size) {
    const float* x    = (const float*)d_in[0];
    const float* Wq   = (const float*)d_in[1];
    const float* bq   = (const float*)d_in[2];
    const float* Wk   = (const float*)d_in[3];
    const float* bk   = (const float*)d_in[4];
    const float* Wv   = (const float*)d_in[5];
    const float* bv   = (const float*)d_in[6];
    const float* ln1w = (const float*)d_in[7];
    const float* ln1b = (const float*)d_in[8];
    const float* ln2w = (const float*)d_in[9];
    const float* ln2b = (const float*)d_in[10];
    float* out = (float*)d_out;

    ln1_wcvt_kernel<<<LN1_BLOCKS + 512, 256>>>(x, ln1w, ln1b, Wq, Wk, Wv);

    cudaFuncSetAttribute(qkv_gemm_kernel, cudaFuncAttributeMaxDynamicSharedMemorySize,
                         GEMM2_SMEM);
    qkv_gemm_kernel<<<dim3(BT / 128, Hdim / 128, 24), 256, GEMM2_SMEM>>>(bq, bk, bv);

    cudaFuncSetAttribute(attn_kernel, cudaFuncAttributeMaxDynamicSharedMemorySize,
                         ATT3_SMEM);
    attn_kernel<<<dim3(Tdim / 128, Bdim, NBR), 256, ATT3_SMEM>>>();

    ln2_kernel<<<BT, Hdim>>>(ln2w, ln2b, out);
}